// round 1
// baseline (speedup 1.0000x reference)
#include <cuda_runtime.h>
#include <math.h>

#define NB      2048
#define EXPR    8000
#define H1      1024
#define H2      100
#define M_TOT   4096
#define DD      78
#define DN      200
#define NPG     64
#define EPG     128
#define NG      2048
#define ET_TOT  262144
#define KTOP    52

__device__ float g_h1[M_TOT * H1];     // 16.8 MB scratch
__device__ float g_dx[NG * 400];       // 3.3 MB scratch

// ============================================================================
// GEMM1: h1 = relu(((x*bn0_s + bn0_t) @ W1^T + b1)*bn1_s + bn1_t)
// M=4096 (x1 rows 0..2047, x2 rows 2048..4095), N=1024, K=8000
// ============================================================================
#define G1_BM 128
#define G1_BN 64
#define G1_BK 16
#define G1_PAD 17

__global__ __launch_bounds__(256) void gemm1_kernel(
    const float* __restrict__ x1, const float* __restrict__ x2,
    const float* __restrict__ W1, const float* __restrict__ b1,
    const float* __restrict__ bn0_s, const float* __restrict__ bn0_t,
    const float* __restrict__ bn1_s, const float* __restrict__ bn1_t)
{
    __shared__ float As[G1_BM * G1_PAD];
    __shared__ float Bs[G1_BN * G1_PAD];

    const int tid = threadIdx.x;
    const int tx = tid & 15;          // 0..15 -> 4 cols each
    const int ty = tid >> 4;          // 0..15 -> 8 rows each
    const int brow = blockIdx.y;      // 0..31
    const int bcol = blockIdx.x;      // 0..15

    const float* X = (brow < 16) ? x1 : x2;
    const int rowbase = (brow & 15) * G1_BM;
    const int colbase = bcol * G1_BN;

    // A tile: 128x16 = 512 float4, 2 per thread. B tile: 64x16 = 256 float4, 1 per thread.
    const int ra0 = tid >> 2,         ca0 = (tid & 3) * 4;
    const int ra1 = (tid + 256) >> 2, ca1 = ((tid + 256) & 3) * 4;
    const int rb  = tid >> 2,         cb  = (tid & 3) * 4;

    const float* pA0 = X + (size_t)(rowbase + ra0) * EXPR + ca0;
    const float* pA1 = X + (size_t)(rowbase + ra1) * EXPR + ca1;
    const float* pB  = W1 + (size_t)(colbase + rb) * EXPR + cb;

    float4 pa0, pa1, pb4, s0, t0, s1, t1;

    // initial load
    {
        pa0 = *(const float4*)(pA0);
        pa1 = *(const float4*)(pA1);
        pb4 = *(const float4*)(pB);
        s0 = *(const float4*)&bn0_s[ca0];  t0 = *(const float4*)&bn0_t[ca0];
        s1 = *(const float4*)&bn0_s[ca1];  t1 = *(const float4*)&bn0_t[ca1];
    }
    // store tile 0
    As[ra0*G1_PAD + ca0 + 0] = pa0.x*s0.x + t0.x;
    As[ra0*G1_PAD + ca0 + 1] = pa0.y*s0.y + t0.y;
    As[ra0*G1_PAD + ca0 + 2] = pa0.z*s0.z + t0.z;
    As[ra0*G1_PAD + ca0 + 3] = pa0.w*s0.w + t0.w;
    As[ra1*G1_PAD + ca1 + 0] = pa1.x*s1.x + t1.x;
    As[ra1*G1_PAD + ca1 + 1] = pa1.y*s1.y + t1.y;
    As[ra1*G1_PAD + ca1 + 2] = pa1.z*s1.z + t1.z;
    As[ra1*G1_PAD + ca1 + 3] = pa1.w*s1.w + t1.w;
    Bs[rb*G1_PAD + cb + 0] = pb4.x;
    Bs[rb*G1_PAD + cb + 1] = pb4.y;
    Bs[rb*G1_PAD + cb + 2] = pb4.z;
    Bs[rb*G1_PAD + cb + 3] = pb4.w;
    __syncthreads();

    float acc[8][4];
    #pragma unroll
    for (int i = 0; i < 8; ++i)
        #pragma unroll
        for (int j = 0; j < 4; ++j) acc[i][j] = 0.f;

    const int NT_K = EXPR / G1_BK;  // 500
    for (int kt = 0; kt < NT_K; ++kt) {
        const bool has = (kt + 1) < NT_K;
        const int k0n = (kt + 1) * G1_BK;
        if (has) {
            pa0 = *(const float4*)(pA0 + k0n);
            pa1 = *(const float4*)(pA1 + k0n);
            pb4 = *(const float4*)(pB + k0n);
            s0 = *(const float4*)&bn0_s[k0n + ca0];  t0 = *(const float4*)&bn0_t[k0n + ca0];
            s1 = *(const float4*)&bn0_s[k0n + ca1];  t1 = *(const float4*)&bn0_t[k0n + ca1];
        }
        #pragma unroll
        for (int kk = 0; kk < G1_BK; ++kk) {
            float a[8], bb[4];
            #pragma unroll
            for (int i = 0; i < 8; ++i) a[i] = As[(ty*8 + i)*G1_PAD + kk];
            #pragma unroll
            for (int j = 0; j < 4; ++j) bb[j] = Bs[(tx*4 + j)*G1_PAD + kk];
            #pragma unroll
            for (int i = 0; i < 8; ++i)
                #pragma unroll
                for (int j = 0; j < 4; ++j) acc[i][j] += a[i] * bb[j];
        }
        __syncthreads();
        if (has) {
            As[ra0*G1_PAD + ca0 + 0] = pa0.x*s0.x + t0.x;
            As[ra0*G1_PAD + ca0 + 1] = pa0.y*s0.y + t0.y;
            As[ra0*G1_PAD + ca0 + 2] = pa0.z*s0.z + t0.z;
            As[ra0*G1_PAD + ca0 + 3] = pa0.w*s0.w + t0.w;
            As[ra1*G1_PAD + ca1 + 0] = pa1.x*s1.x + t1.x;
            As[ra1*G1_PAD + ca1 + 1] = pa1.y*s1.y + t1.y;
            As[ra1*G1_PAD + ca1 + 2] = pa1.z*s1.z + t1.z;
            As[ra1*G1_PAD + ca1 + 3] = pa1.w*s1.w + t1.w;
            Bs[rb*G1_PAD + cb + 0] = pb4.x;
            Bs[rb*G1_PAD + cb + 1] = pb4.y;
            Bs[rb*G1_PAD + cb + 2] = pb4.z;
            Bs[rb*G1_PAD + cb + 3] = pb4.w;
            __syncthreads();
        }
    }

    // epilogue: relu(acc*bn1_s + b1*bn1_s + bn1_t)
    float alpha[4], beta[4];
    #pragma unroll
    for (int j = 0; j < 4; ++j) {
        int n = colbase + tx*4 + j;
        alpha[j] = bn1_s[n];
        beta[j]  = b1[n]*alpha[j] + bn1_t[n];
    }
    #pragma unroll
    for (int i = 0; i < 8; ++i) {
        int m = brow*G1_BM + ty*8 + i;
        float4 v;
        v.x = fmaxf(acc[i][0]*alpha[0] + beta[0], 0.f);
        v.y = fmaxf(acc[i][1]*alpha[1] + beta[1], 0.f);
        v.z = fmaxf(acc[i][2]*alpha[2] + beta[2], 0.f);
        v.w = fmaxf(acc[i][3]*alpha[3] + beta[3], 0.f);
        *(float4*)&g_h1[(size_t)m*H1 + colbase + tx*4] = v;
    }
}

// ============================================================================
// GEMM2: f = relu((h1 @ W2^T + b2)*bn2_s + bn2_t); rows<2048 -> f1, else f2
// M=4096, K=1024, N=100.  Block: 32 rows. Thread: 2 rows x 7 cols.
// ============================================================================
#define G2_BK 16

__global__ __launch_bounds__(256) void gemm2_kernel(
    const float* __restrict__ W2, const float* __restrict__ b2,
    const float* __restrict__ bn2_s, const float* __restrict__ bn2_t,
    float* __restrict__ out)
{
    __shared__ float As[32 * G2_BK];
    __shared__ float Bs[112 * 17];

    const int tid = threadIdx.x;
    const int tx = tid & 15;     // col group
    const int ty = tid >> 4;     // row base
    const int m0 = blockIdx.x * 32;

    const int rowA = tid >> 3, c2 = (tid & 7) * 2;
    const float* pA = g_h1 + (size_t)(m0 + rowA) * H1 + c2;

    float2 aPre;
    float  bPre[7];

    // load tile 0
    aPre = *(const float2*)(pA);
    #pragma unroll
    for (int it = 0; it < 7; ++it) {
        int i = tid + it*256;
        if (i < 1600) bPre[it] = W2[(size_t)(i/16) * H1 + (i & 15)];
    }
    As[rowA*G2_BK + c2] = aPre.x;  As[rowA*G2_BK + c2 + 1] = aPre.y;
    #pragma unroll
    for (int it = 0; it < 7; ++it) {
        int i = tid + it*256;
        if (i < 1600) Bs[(i/16)*17 + (i & 15)] = bPre[it];
    }
    __syncthreads();

    float acc0[7], acc1[7];
    #pragma unroll
    for (int j = 0; j < 7; ++j) { acc0[j] = 0.f; acc1[j] = 0.f; }

    const int NT_K = H1 / G2_BK;  // 64
    for (int kt = 0; kt < NT_K; ++kt) {
        const bool has = (kt + 1) < NT_K;
        const int k0n = (kt + 1) * G2_BK;
        if (has) {
            aPre = *(const float2*)(pA + k0n);
            #pragma unroll
            for (int it = 0; it < 7; ++it) {
                int i = tid + it*256;
                if (i < 1600) bPre[it] = W2[(size_t)(i/16) * H1 + k0n + (i & 15)];
            }
        }
        #pragma unroll
        for (int kk = 0; kk < G2_BK; ++kk) {
            float a0 = As[ty*G2_BK + kk];
            float a1 = As[(ty + 16)*G2_BK + kk];
            #pragma unroll
            for (int j = 0; j < 7; ++j) {
                float bv = Bs[(tx + 16*j)*17 + kk];
                acc0[j] += a0 * bv;
                acc1[j] += a1 * bv;
            }
        }
        __syncthreads();
        if (has) {
            As[rowA*G2_BK + c2] = aPre.x;  As[rowA*G2_BK + c2 + 1] = aPre.y;
            #pragma unroll
            for (int it = 0; it < 7; ++it) {
                int i = tid + it*256;
                if (i < 1600) Bs[(i/16)*17 + (i & 15)] = bPre[it];
            }
            __syncthreads();
        }
    }

    #pragma unroll
    for (int j = 0; j < 7; ++j) {
        int n = tx + 16*j;
        if (n >= H2) continue;
        float al = bn2_s[n];
        float be = b2[n]*al + bn2_t[n];
        int m_a = m0 + ty, m_b = m0 + ty + 16;
        float va = fmaxf(acc0[j]*al + be, 0.f);
        float vb = fmaxf(acc1[j]*al + be, 0.f);
        size_t oa = (m_a < NB) ? ((size_t)m_a*H2 + n) : ((size_t)NB*H2 + (size_t)(m_a - NB)*H2 + n);
        size_t ob = (m_b < NB) ? ((size_t)m_b*H2 + n) : ((size_t)NB*H2 + (size_t)(m_b - NB)*H2 + n);
        out[oa] = va;
        out[ob] = vb;
    }
}

// ============================================================================
// Drug encoder: one CTA per graph. Everything in SMEM.
// ============================================================================
#define XPAD 79
#define HPAD 201
#define SM_WREL   0
#define SM_WROOT  (SM_WREL  + DD*DN)         // 15600
#define SM_XS     (SM_WROOT + DD*DN)         // 15600
#define SM_AGG    (SM_XS    + NPG*XPAD)      // 5056
#define SM_H      (SM_AGG   + NPG*XPAD)      // 5056
#define SM_TW     (SM_H     + NPG*HPAD)      // 12864
#define SM_SCORE  (SM_TW    + DN)            // 200
#define SM_RED    (SM_SCORE + NPG)           // 64
#define SM_FLOATS (SM_RED   + 1)
#define SM_DRUG_BYTES (SM_FLOATS*4 + (NPG + 2*EPG)*4)

__global__ __launch_bounds__(256) void drug_kernel(
    const float* __restrict__ drug_x, const int* __restrict__ edge_index,
    const float* __restrict__ Wrel, const float* __restrict__ brel,
    const float* __restrict__ Wroot,
    const float* __restrict__ bnd_s, const float* __restrict__ bnd_t,
    const float* __restrict__ topk_w)
{
    extern __shared__ float sm[];
    float* WrelT  = sm + SM_WREL;    // [d][c] transposed
    float* WrootT = sm + SM_WROOT;
    float* xs     = sm + SM_XS;      // [n][79]
    float* agg    = sm + SM_AGG;
    float* hsh    = sm + SM_H;       // [n][201]
    float* tw     = sm + SM_TW;
    float* score  = sm + SM_SCORE;
    float* red    = sm + SM_RED;
    int* flag = (int*)(sm + SM_FLOATS);
    int* es   = flag + NPG;
    int* ed   = es + EPG;

    const int g = blockIdx.x;
    const int tid = threadIdx.x;

    // stage weights transposed (float2-vectorized broadcast reads later)
    for (int i = tid; i < DN*DD; i += 256) {
        int c = i / DD, d = i % DD;
        WrelT[d*DN + c]  = Wrel[i];
        WrootT[d*DN + c] = Wroot[i];
    }
    for (int i = tid; i < NPG*DD; i += 256) {
        int n = i / DD, d = i % DD;
        xs[n*XPAD + d]  = drug_x[(size_t)(g*NPG + n)*DD + d];
        agg[n*XPAD + d] = 0.f;
    }
    if (tid < DN) tw[tid] = topk_w[tid];
    if (tid < EPG) {
        es[tid] = edge_index[g*EPG + tid] - g*NPG;
        ed[tid] = edge_index[ET_TOT + g*EPG + tid] - g*NPG;
    }
    if (tid == 0) red[0] = 0.f;
    __syncthreads();

    if (tid < DN) atomicAdd(&red[0], tw[tid]*tw[tid]);
    // edge aggregation: one thread per feature dim, sequential over edges (no races)
    if (tid < DD) {
        const int d = tid;
        for (int e = 0; e < EPG; ++e)
            agg[ed[e]*XPAD + d] += xs[es[e]*XPAD + d];
    }
    __syncthreads();

    // node GEMM: h[n][c] = relu((agg.Wrel + x.Wroot + brel)*s + t)
    const int n = tid & 63;
    const int txg = tid >> 6;           // 0..3
    const int cbase = txg * 50;
    float acc[50];
    #pragma unroll
    for (int j = 0; j < 50; ++j) acc[j] = 0.f;

    const float* ap = &agg[n*XPAD];
    const float* xp = &xs[n*XPAD];
    for (int d = 0; d < DD; ++d) {
        float av = ap[d], xv = xp[d];
        const float2* wr = (const float2*)&WrelT[d*DN + cbase];
        const float2* wo = (const float2*)&WrootT[d*DN + cbase];
        #pragma unroll
        for (int j2 = 0; j2 < 25; ++j2) {
            float2 r2 = wr[j2], o2 = wo[j2];
            acc[2*j2]   += av*r2.x + xv*o2.x;
            acc[2*j2+1] += av*r2.y + xv*o2.y;
        }
    }
    #pragma unroll
    for (int j = 0; j < 50; ++j) {
        int c = cbase + j;
        float v = (acc[j] + brel[c]) * bnd_s[c] + bnd_t[c];
        hsh[n*HPAD + c] = fmaxf(v, 0.f);
    }
    __syncthreads();

    // TopK score
    if (tid < NPG) {
        float s = 0.f;
        const float* hp = &hsh[tid*HPAD];
        for (int c = 0; c < DN; ++c) s += hp[c]*tw[c];
        score[tid] = tanhf(s * rsqrtf(red[0]));
    }
    __syncthreads();
    // stable rank (matches jax top_k tie-breaking: lower index wins)
    if (tid < NPG) {
        float sn = score[tid];
        int r = 0;
        for (int m2 = 0; m2 < NPG; ++m2) {
            float sv = score[m2];
            r += (sv > sn) || (sv == sn && m2 < tid);
        }
        flag[tid] = (r < KTOP) ? 1 : 0;
    }
    __syncthreads();

    // readouts: mm0 (all nodes), mm1 (topk scaled); dx = relu(mm0 + 3*mm1)
    if (tid < DN) {
        const int c = tid;
        float mx = -1e30f, sum = 0.f, mxs = -1e30f, sums = 0.f;
        for (int n2 = 0; n2 < NPG; ++n2) {
            float v = hsh[n2*HPAD + c];
            mx = fmaxf(mx, v); sum += v;
            if (flag[n2]) {
                float w = v * score[n2];
                mxs = fmaxf(mxs, w); sums += w;
            }
        }
        g_dx[(size_t)g*400 + c]       = fmaxf(mx + 3.f*mxs, 0.f);
        g_dx[(size_t)g*400 + DN + c]  = fmaxf(sum*(1.f/NPG) + 3.f*(sums*(1.f/KTOP)), 0.f);
    }
}

// ============================================================================
// resp = [f1 | dx] @ Wp^T + bp
// ============================================================================
__global__ __launch_bounds__(256) void resp_kernel(
    const float* __restrict__ Wp, const float* __restrict__ bp,
    float* __restrict__ out)
{
    const int row = blockIdx.x * 8 + (threadIdx.x >> 5);
    const int lane = threadIdx.x & 31;
    float s = 0.f;
    for (int i = lane; i < 500; i += 32) {
        float z = (i < H2) ? out[(size_t)row*H2 + i] : g_dx[(size_t)row*400 + (i - H2)];
        s += z * Wp[i];
    }
    #pragma unroll
    for (int o = 16; o; o >>= 1) s += __shfl_down_sync(0xffffffffu, s, o);
    if (lane == 0) out[(size_t)2*NB*H2 + row] = s + bp[0];
}

// ============================================================================
extern "C" void kernel_launch(void* const* d_in, const int* in_sizes, int n_in,
                              void* d_out, int out_size)
{
    const float* x1     = (const float*)d_in[0];
    const float* x2     = (const float*)d_in[1];
    // d_in[2] batch_idx, d_in[3] edge_attr: unused
    const int*   eidx   = (const int*)d_in[4];
    const float* drug_x = (const float*)d_in[5];
    const float* bn0_s  = (const float*)d_in[6];
    const float* bn0_t  = (const float*)d_in[7];
    const float* W1     = (const float*)d_in[8];
    const float* b1     = (const float*)d_in[9];
    const float* bn1_s  = (const float*)d_in[10];
    const float* bn1_t  = (const float*)d_in[11];
    const float* W2     = (const float*)d_in[12];
    const float* b2     = (const float*)d_in[13];
    const float* bn2_s  = (const float*)d_in[14];
    const float* bn2_t  = (const float*)d_in[15];
    const float* Wrel   = (const float*)d_in[16];
    const float* brel   = (const float*)d_in[17];
    const float* Wroot  = (const float*)d_in[18];
    const float* bnd_s  = (const float*)d_in[19];
    const float* bnd_t  = (const float*)d_in[20];
    const float* topk_w = (const float*)d_in[21];
    const float* Wp     = (const float*)d_in[22];
    const float* bp     = (const float*)d_in[23];
    float* out = (float*)d_out;

    cudaFuncSetAttribute(drug_kernel, cudaFuncAttributeMaxDynamicSharedMemorySize,
                         SM_DRUG_BYTES);

    dim3 g1(H1 / G1_BN, M_TOT / G1_BM);   // (16, 32)
    gemm1_kernel<<<g1, 256>>>(x1, x2, W1, b1, bn0_s, bn0_t, bn1_s, bn1_t);
    gemm2_kernel<<<M_TOT / 32, 256>>>(W2, b2, bn2_s, bn2_t, out);
    drug_kernel<<<NG, 256, SM_DRUG_BYTES>>>(drug_x, eidx, Wrel, brel, Wroot,
                                            bnd_s, bnd_t, topk_w);
    resp_kernel<<<NG / 8, 256>>>(Wp, bp, out);
}